// round 6
// baseline (speedup 1.0000x reference)
#include <cuda_runtime.h>
#include <cuda_fp16.h>
#include <math.h>

#define NN 100000
#define NE 1600000
#define NC 2000
#define NF 64
#define EFD 41
#define HF 128
#define DIN 169

typedef unsigned long long ull;

// ---------------- scratch (static __device__, no allocations) ----------------
__device__ float   g_X[NN * NF];            // node features              25.6MB
__device__ __half  g_P1h[NN * HF];          // X @ Wf[0:64]   fp16       25.6MB
__device__ __half  g_P2h[NN * HF];          // X @ Wf[64:128] fp16       25.6MB
__device__ float   g_EFS[(size_t)NE * EFD]; // edge features sorted     262.4MB
__device__ int     g_I1S[NE], g_I2S[NE];    // endpoints sorted order
__device__ float   g_ACC[NN * NF];          // per-node msg SUMS
__device__ float   g_T[NN * NF];            // T_n = sum_{e:i1=n} x[i2]  25.6MB
__device__ float   g_S1[NN * EFD];          // per-node ef sums by idx1  16.4MB
__device__ float   g_S2[NN * EFD];          // per-node ef sums by idx2  16.4MB
__device__ int     g_DEG[NN], g_DEG2[NN];
__device__ float   g_D1f[NN], g_D2f[NN];    // deg as float
__device__ float   g_DIf[NN];               // 1/max(deg1,1)
__device__ float   g_SCR[NN];               // scratch (unused inverse for idx2 sort)
__device__ int     g_CNT[NC];
__device__ float   g_CRY[NC * NF];
__device__ double  g_NS[2 * NF];            // node BN sum / sumsq
__device__ float   g_AF[2 * HF];            // edge BN scale/shift
__device__ float   g_NAF[2 * NF];           // node BN scale/shift
// per-layer Gram accumulators (double), one flat array:
// [0:4096) G11, [4096:8192) G12, [8192:10816) G13(64x41),
// [10816:14912) G22, [14912:17536) G23(64x41), [17536:17664) su1|su2
#define OFF11 0
#define OFF12 4096
#define OFF13 8192
#define OFF22 10816
#define OFF23 14912
#define OFFSU 17536
#define GLD_N 17664
__device__ double  g_GLd[GLD_N];
__device__ double  g_G33d[EFD * EFD];       // setup-only
__device__ double  g_sefd[EFD];             // setup-only
// counting-sort infra
__device__ int g_TMP[NN];
__device__ int g_BS[512];
__device__ int g_BSX[512];
__device__ int g_START[NN],  g_CUR[NN],  g_ESRC[NE];
__device__ int g_START2[NN], g_CUR2[NN], g_ESRC2[NE];

// ---------------- helpers ----------------
__device__ __forceinline__ ull pack2(float x) {
    ull r; asm("mov.b64 %0, {%1, %1};" : "=l"(r) : "f"(x)); return r;
}
__device__ __forceinline__ ull packf2(float x, float y) {
    ull r; asm("mov.b64 %0, {%1, %2};" : "=l"(r) : "f"(x), "f"(y)); return r;
}
__device__ __forceinline__ void ffma2(ull& d, ull a, ull b) {
    asm("fma.rn.f32x2 %0, %1, %2, %0;" : "+l"(d) : "l"(a), "l"(b));
}
__device__ __forceinline__ float2 unpk(ull v) {
    float2 r; asm("mov.b64 {%0, %1}, %2;" : "=f"(r.x), "=f"(r.y) : "l"(v)); return r;
}
__device__ __forceinline__ float sp_f(float x) {
    return fmaxf(x, 0.f) + __logf(1.f + __expf(-fabsf(x)));
}
__device__ __forceinline__ float sig_f(float x) {
    return __fdividef(1.f, 1.f + __expf(-x));
}
__device__ __forceinline__ float2 h2f(unsigned u) {
    __half2 h = *(__half2*)&u; return __half22float2(h);
}

// ---------------- setup kernels ----------------
__global__ void k_pre() {
    int i = blockIdx.x * 256 + threadIdx.x;     // 500*256 = 128000
    if (i < NN) { g_DEG[i] = 0; g_DEG2[i] = 0; }
    if (i < NC) g_CNT[i] = 0;
    if (i < NC * NF) g_CRY[i] = 0.f;
    if (i < EFD * EFD) g_G33d[i] = 0.0;
    if (i < EFD) g_sefd[i] = 0.0;
}

__global__ void k_embed(const int* __restrict__ nf, const float* __restrict__ emb) {
    int i = blockIdx.x * 256 + threadIdx.x;     // NN*16
    if (i >= NN * 16) return;
    int n = i >> 4, c = i & 15;
    int v = nf[n];
    float4 val = ((const float4*)(emb + (size_t)v * NF))[c];
    ((float4*)(g_X + (size_t)n * NF))[c] = val;
}

__global__ void k_deg(const int* __restrict__ idx, int* deg) {
    int e = blockIdx.x * 256 + threadIdx.x;
    if (e < NE) atomicAdd(&deg[idx[e]], 1);
}

__global__ void k_cnt3(const int* __restrict__ idx3) {
    int n = blockIdx.x * 256 + threadIdx.x;
    if (n < NN) atomicAdd(&g_CNT[idx3[n]], 1);
}

// ---------------- counting sort (parameterized) ----------------
__global__ void k_scan1(const int* __restrict__ deg) {
    __shared__ int s[256];
    int tid = threadIdx.x;
    int n = blockIdx.x * 256 + tid;
    int d = (n < NN) ? deg[n] : 0;
    s[tid] = d;
    __syncthreads();
    for (int off = 1; off < 256; off <<= 1) {
        int v = (tid >= off) ? s[tid - off] : 0;
        __syncthreads();
        s[tid] += v;
        __syncthreads();
    }
    if (n < NN) g_TMP[n] = s[tid] - d;
    if (tid == 255) g_BS[blockIdx.x] = s[255];
}

__global__ void k_scan2() {
    __shared__ int s[512];
    int tid = threadIdx.x;
    int d = (tid < 391) ? g_BS[tid] : 0;
    s[tid] = d;
    __syncthreads();
    for (int off = 1; off < 512; off <<= 1) {
        int v = (tid >= off) ? s[tid - off] : 0;
        __syncthreads();
        s[tid] += v;
        __syncthreads();
    }
    if (tid < 391) g_BSX[tid] = s[tid] - d;
}

__global__ void k_scan3(const int* __restrict__ deg, int* start, int* cur,
                        float* df, float* di) {
    int n = blockIdx.x * 256 + threadIdx.x;
    if (n < NN) {
        int st = g_TMP[n] + g_BSX[blockIdx.x];
        start[n] = st;
        cur[n] = st;
        int d = deg[n];
        df[n] = (float)d;
        di[n] = 1.f / (float)max(d, 1);
    }
}

__global__ void k_perm(const int* __restrict__ idx, int* cur, int* esrc) {
    int e = blockIdx.x * 256 + threadIdx.x;
    if (e < NE) {
        int pos = atomicAdd(&cur[idx[e]], 1);
        esrc[pos] = e;
    }
}

__global__ void k_permidx(const int* __restrict__ idx1, const int* __restrict__ idx2) {
    int p = blockIdx.x * 256 + threadIdx.x;
    if (p < NE) {
        int e = g_ESRC[p];
        g_I1S[p] = idx1[e];
        g_I2S[p] = idx2[e];
    }
}

__global__ void k_permef(const float* __restrict__ ef) {
    size_t i = (size_t)blockIdx.x * 256 + threadIdx.x;   // NE*EFD total
    if (i >= (size_t)NE * EFD) return;
    int p = (int)(i / EFD), c = (int)(i - (size_t)p * EFD);
    g_EFS[i] = __ldg(ef + (size_t)g_ESRC[p] * EFD + c);
}

// per-node ef sums over idx1 segments (reads sorted EFS, coalesced)
__global__ void k_S1() {
    int t = threadIdx.x;
    int n = blockIdx.x * 4 + (t >> 6);   // 25000 blocks * 4 = NN
    int f = t & 63;
    if (f >= EFD) return;
    int st = g_START[n], dg = g_DEG[n];
    float s = 0.f;
    const float* p = g_EFS + (size_t)st * EFD + f;
    for (int q = 0; q < dg; q++) s += __ldcs(p + (size_t)q * EFD);
    g_S1[(size_t)n * EFD + f] = s;
}

// per-node ef sums over idx2 segments (random gather from original ef)
__global__ void k_S2(const float* __restrict__ ef) {
    int t = threadIdx.x;
    int n = blockIdx.x * 4 + (t >> 6);
    int f = t & 63;
    if (f >= EFD) return;
    int st = g_START2[n], dg = g_DEG2[n];
    float s = 0.f;
    for (int q = 0; q < dg; q++) {
        int e = g_ESRC2[st + q];
        s += __ldg(ef + (size_t)e * EFD + f);
    }
    g_S2[(size_t)n * EFD + f] = s;
}

// G33 = sum_e ef ef^T and sef = sum_e ef  (from sorted EFS, coalesced)
__global__ __launch_bounds__(256) void k_G33() {
    __shared__ float se[32][EFD + 1];
    int tid = threadIdx.x;
    // precompute this thread's 7 (a,b) pairs once
    int pa[7], pb[7];
    bool pv[7];
    #pragma unroll
    for (int i = 0; i < 7; i++) {
        int p = tid * 7 + i;
        pv[i] = (p < EFD * EFD);
        int a = pv[i] ? (p / EFD) : 0;
        pa[i] = a;
        pb[i] = pv[i] ? (p - a * EFD) : 0;
    }
    float acc[7];
    #pragma unroll
    for (int i = 0; i < 7; i++) acc[i] = 0.f;
    float sef = 0.f;
    size_t e0 = (size_t)blockIdx.x * 3125;     // 512*3125 = NE
    for (int base = 0; base < 3125; base += 32) {
        int cnt = min(32, 3125 - base);
        for (int i = tid; i < 32 * EFD; i += 256) {
            int r = i / EFD, c = i - r * EFD;
            se[r][c] = (r < cnt) ? __ldcs(g_EFS + (e0 + base + r) * EFD + c) : 0.f;
        }
        __syncthreads();
        #pragma unroll 1
        for (int r = 0; r < 32; r++) {
            #pragma unroll
            for (int i = 0; i < 7; i++)
                acc[i] += se[r][pa[i]] * se[r][pb[i]];
            if (tid < EFD) sef += se[r][tid];
        }
        __syncthreads();
    }
    #pragma unroll 1
    for (int i = 0; i < 7; i++)
        if (pv[i]) atomicAdd(&g_G33d[tid * 7 + i], (double)acc[i]);
    if (tid < EFD) atomicAdd(&g_sefd[tid], (double)sef);
}

// ---------------- per-layer kernels ----------------
__global__ void k_zlayer() {
    for (int i = blockIdx.x * 256 + threadIdx.x; i < NN * NF; i += gridDim.x * 256) {
        g_ACC[i] = 0.f;
        if (i < GLD_N) g_GLd[i] = 0.0;
        if (i < 2 * NF) g_NS[i] = 0.0;
    }
}

// node GEMM: P1/P2(half) = X @ Wf[l][half*64 : +64]
__global__ __launch_bounds__(256) void k_nodegemm(const float* __restrict__ Wf, int layer) {
    __shared__ float sW[64 * HF];
    __shared__ float sX[64 * NF];
    const float* Wb = Wf + ((size_t)layer * DIN + blockIdx.y * 64) * HF;
    int tid = threadIdx.x;
    #pragma unroll 4
    for (int i = tid; i < 64 * HF; i += 256) sW[i] = Wb[i];
    int n0 = blockIdx.x * 64;
    for (int i = tid; i < 64 * NF; i += 256) {
        int r = i >> 6, c = i & 63, n = n0 + r;
        sX[i] = (n < NN) ? g_X[(size_t)n * NF + c] : 0.f;
    }
    __syncthreads();
    int fg = tid & 15, eg = tid >> 4;
    int fa = fg * 4, fb = 64 + fg * 4;
    ull acc[4][4];
    #pragma unroll
    for (int j = 0; j < 4; j++)
        #pragma unroll
        for (int q = 0; q < 4; q++) acc[j][q] = 0ULL;
    #pragma unroll 1
    for (int k = 0; k < 64; k++) {
        ulonglong2 wa = *(const ulonglong2*)(sW + k * HF + fa);
        ulonglong2 wb = *(const ulonglong2*)(sW + k * HF + fb);
        #pragma unroll
        for (int j = 0; j < 4; j++) {
            ull a = pack2(sX[(eg * 4 + j) * NF + k]);
            ffma2(acc[j][0], a, wa.x); ffma2(acc[j][1], a, wa.y);
            ffma2(acc[j][2], a, wb.x); ffma2(acc[j][3], a, wb.y);
        }
    }
    __half* out = blockIdx.y ? g_P2h : g_P1h;
    #pragma unroll
    for (int j = 0; j < 4; j++) {
        int n = n0 + eg * 4 + j;
        if (n < NN) {
            float2 v0 = unpk(acc[j][0]), v1 = unpk(acc[j][1]);
            float2 v2 = unpk(acc[j][2]), v3 = unpk(acc[j][3]);
            __half2 ha[2], hb[2];
            ha[0] = __floats2half2_rn(v0.x, v0.y);
            ha[1] = __floats2half2_rn(v1.x, v1.y);
            hb[0] = __floats2half2_rn(v2.x, v2.y);
            hb[1] = __floats2half2_rn(v3.x, v3.y);
            *(uint2*)(out + (size_t)n * HF + fa) = *(uint2*)ha;
            *(uint2*)(out + (size_t)n * HF + fb) = *(uint2*)hb;
        }
    }
}

// T_n = sum over idx1-segment of x[i2]
__global__ void k_T() {
    int t = threadIdx.x;
    int n = blockIdx.x * 4 + (t >> 6);
    int f = t & 63;
    int st = g_START[n], dg = g_DEG[n];
    float s = 0.f;
    for (int q = 0; q < dg; q++) {
        int i2 = g_I2S[st + q];
        s += g_X[(size_t)i2 * NF + f];
    }
    g_T[(size_t)n * NF + f] = s;
}

// Gram accumulation: rows = x (64), cols = [d1x(64), T(64), S1(41), d2x(64), S2(41)] = 274, pad 276
__global__ __launch_bounds__(256) void k_gram() {
    __shared__ float sx[4][64];
    __shared__ float srhs[4][276];
    __shared__ float sd1[4], sd2[4];
    int tid = threadIdx.x;
    int r = tid >> 2, cq = tid & 3;
    float acc[69];
    #pragma unroll
    for (int k = 0; k < 69; k++) acc[k] = 0.f;
    float su1 = 0.f, su2 = 0.f;
    int n0 = blockIdx.x * 782;                 // 128*782 = 100096 >= NN
    int n1 = min(NN, n0 + 782);
    for (int nb = n0; nb < n1; nb += 4) {
        int nvalid = n1 - nb; if (nvalid > 4) nvalid = 4;
        if (tid < 8) {
            int j = tid & 3;
            float v = (j < nvalid) ? ((tid < 4) ? g_D1f[nb + j] : g_D2f[nb + j]) : 0.f;
            if (tid < 4) sd1[j] = v; else sd2[j] = v;
        }
        {
            int j = tid >> 6, c = tid & 63;
            sx[j][c] = (j < nvalid) ? g_X[(size_t)(nb + j) * NF + c] : 0.f;
        }
        __syncthreads();
        #pragma unroll 1
        for (int i = tid; i < 4 * 276; i += 256) {
            int j = i / 276, c = i - j * 276;
            float v = 0.f;
            if (j < nvalid) {
                if (c < 64)       v = sd1[j] * sx[j][c];
                else if (c < 128) v = g_T[(size_t)(nb + j) * NF + (c - 64)];
                else if (c < 169) v = g_S1[(size_t)(nb + j) * EFD + (c - 128)];
                else if (c < 233) v = sd2[j] * sx[j][c - 169];
                else if (c < 274) v = g_S2[(size_t)(nb + j) * EFD + (c - 233)];
            }
            srhs[j][c] = v;
        }
        __syncthreads();
        #pragma unroll 1
        for (int j = 0; j < 4; j++) {
            float xr = sx[j][r];
            const float* rp = &srhs[j][cq * 69];
            #pragma unroll
            for (int k = 0; k < 69; k++) acc[k] += xr * rp[k];
            if (cq == 0) { su1 += sd1[j] * xr; su2 += sd2[j] * xr; }
        }
        __syncthreads();
    }
    #pragma unroll 1
    for (int k = 0; k < 69; k++) {
        int c = cq * 69 + k;
        if (c < 274) {
            int off;
            if (c < 64)       off = OFF11 + r * 64 + c;
            else if (c < 128) off = OFF12 + r * 64 + (c - 64);
            else if (c < 169) off = OFF13 + r * EFD + (c - 128);
            else if (c < 233) off = OFF22 + r * 64 + (c - 169);
            else              off = OFF23 + r * EFD + (c - 233);
            atomicAdd(&g_GLd[off], (double)acc[k]);
        }
    }
    if (cq == 0) {
        atomicAdd(&g_GLd[OFFSU + r], (double)su1);
        atomicAdd(&g_GLd[OFFSU + 64 + r], (double)su2);
    }
}

// finalize edge BN stats per output feature f
__global__ void k_statfin(const float* __restrict__ Wf, const float* __restrict__ bfp,
                          const float* __restrict__ g1, const float* __restrict__ be1,
                          int layer) {
    __shared__ float sw[DIN];
    __shared__ float red1[256], red2[256];
    int f = blockIdx.x, tid = threadIdx.x;     // 128 blocks, 256 threads
    const float* W = Wf + (size_t)layer * DIN * HF;
    if (tid < DIN) sw[tid] = W[(size_t)tid * HF + f];
    __syncthreads();
    float rowv = 0.f, dotv = 0.f;
    if (tid < DIN) {
        int r = tid;
        float wr = sw[r];
        float s = 0.f;
        if (r < 64) {
            const double* g11 = g_GLd + OFF11 + r * 64;
            const double* g12 = g_GLd + OFF12 + r * 64;
            const double* g13 = g_GLd + OFF13 + r * EFD;
            for (int c = 0; c < 64; c++)  s += (float)g11[c] * sw[c];
            float s2 = 0.f, s3 = 0.f;
            for (int c = 0; c < 64; c++)  s2 += (float)g12[c] * sw[64 + c];
            for (int c = 0; c < EFD; c++) s3 += (float)g13[c] * sw[128 + c];
            s += 2.f * (s2 + s3);
            dotv = wr * (float)g_GLd[OFFSU + r];
        } else if (r < 128) {
            int r2 = r - 64;
            const double* g22 = g_GLd + OFF22 + r2 * 64;
            const double* g23 = g_GLd + OFF23 + r2 * EFD;
            for (int c = 0; c < 64; c++)  s += (float)g22[c] * sw[64 + c];
            float s3 = 0.f;
            for (int c = 0; c < EFD; c++) s3 += (float)g23[c] * sw[128 + c];
            s += 2.f * s3;
            dotv = wr * (float)g_GLd[OFFSU + r];
        } else {
            int r3 = r - 128;
            const double* g33 = g_G33d + r3 * EFD;
            for (int c = 0; c < EFD; c++) s += (float)g33[c] * sw[128 + c];
            dotv = wr * (float)g_sefd[r3];
        }
        rowv = wr * s;
    }
    red1[tid] = rowv; red2[tid] = dotv;
    __syncthreads();
    for (int s = 128; s > 0; s >>= 1) {
        if (tid < s) { red1[tid] += red1[tid + s]; red2[tid] += red2[tid + s]; }
        __syncthreads();
    }
    if (tid == 0) {
        double q = (double)red1[0];
        double dot = (double)red2[0];
        double b = (double)bfp[layer * HF + f];
        double sumz = dot + (double)NE * b;
        double sumz2 = q + 2.0 * b * dot + (double)NE * b * b;
        double mean = sumz / (double)NE;
        double var = sumz2 / (double)NE - mean * mean;
        float istd = (float)rsqrt(var + 1e-5);
        float sc = g1[layer * HF + f] * istd;
        g_AF[f] = sc;
        g_AF[HF + f] = be1[layer * HF + f] - (float)mean * sc;
    }
}

// ---------------- fused edge pass: GEMM + BN + gate*softplus + segment scatter
__global__ __launch_bounds__(256) void k_edgeF(
    const float* __restrict__ Wf, const float* __restrict__ bfp, int layer)
{
    __shared__ float sW[42 * HF];
    __shared__ float sE[128 * 42];
    __shared__ int sI1[128], sI2[128];
    const float* Wb = Wf + ((size_t)layer * DIN + 128) * HF;
    int tid = threadIdx.x;
    for (int i = tid; i < 42 * HF; i += 256) sW[i] = (i < EFD * HF) ? Wb[i] : 0.f;
    size_t p0 = (size_t)blockIdx.x * 128;
    if (tid < 128) {
        sI1[tid] = g_I1S[p0 + tid];
        sI2[tid] = g_I2S[p0 + tid];
    }
    {
        const float* efb = g_EFS + p0 * EFD;
        for (int i = tid; i < 128 * 42; i += 256) {
            int r = i / 42, c = i - r * 42;
            sE[i] = (c < EFD) ? __ldcs(efb + r * EFD + c) : 0.f;
        }
    }
    __syncthreads();

    int fg = tid & 15, eg = tid >> 4;
    int fa = fg * 4, fb = 64 + fg * 4;
    const float* bfl = bfp + layer * HF;
    float4 bva = *(const float4*)(bfl + fa);
    float4 bvb = *(const float4*)(bfl + fb);

    ull acc[8][4];
    #pragma unroll
    for (int j = 0; j < 8; j++) {
        int r = eg * 8 + j;
        int i1 = sI1[r], i2 = sI2[r];
        uint2 u1a = *(const uint2*)(g_P1h + (size_t)i1 * HF + fa);
        uint2 u1b = *(const uint2*)(g_P1h + (size_t)i1 * HF + fb);
        uint2 u2a = *(const uint2*)(g_P2h + (size_t)i2 * HF + fa);
        uint2 u2b = *(const uint2*)(g_P2h + (size_t)i2 * HF + fb);
        float2 p1a0 = h2f(u1a.x), p1a1 = h2f(u1a.y);
        float2 p1b0 = h2f(u1b.x), p1b1 = h2f(u1b.y);
        float2 p2a0 = h2f(u2a.x), p2a1 = h2f(u2a.y);
        float2 p2b0 = h2f(u2b.x), p2b1 = h2f(u2b.y);
        acc[j][0] = packf2(p1a0.x + p2a0.x + bva.x, p1a0.y + p2a0.y + bva.y);
        acc[j][1] = packf2(p1a1.x + p2a1.x + bva.z, p1a1.y + p2a1.y + bva.w);
        acc[j][2] = packf2(p1b0.x + p2b0.x + bvb.x, p1b0.y + p2b0.y + bvb.y);
        acc[j][3] = packf2(p1b1.x + p2b1.x + bvb.z, p1b1.y + p2b1.y + bvb.w);
    }

    #pragma unroll 1
    for (int k = 0; k < 42; k += 2) {
        ulonglong2 wa0 = *(const ulonglong2*)(sW + k * HF + fa);
        ulonglong2 wb0 = *(const ulonglong2*)(sW + k * HF + fb);
        ulonglong2 wa1 = *(const ulonglong2*)(sW + (k + 1) * HF + fa);
        ulonglong2 wb1 = *(const ulonglong2*)(sW + (k + 1) * HF + fb);
        #pragma unroll
        for (int j = 0; j < 8; j++) {
            float2 av = *(const float2*)(sE + (eg * 8 + j) * 42 + k);
            ull a0 = pack2(av.x), a1 = pack2(av.y);
            ffma2(acc[j][0], a0, wa0.x); ffma2(acc[j][1], a0, wa0.y);
            ffma2(acc[j][2], a0, wb0.x); ffma2(acc[j][3], a0, wb0.y);
            ffma2(acc[j][0], a1, wa1.x); ffma2(acc[j][1], a1, wa1.y);
            ffma2(acc[j][2], a1, wb1.x); ffma2(acc[j][3], a1, wb1.y);
        }
    }

    // epilogue: BN + sigmoid*softplus + segment-run accumulate into g_ACC
    float scA0 = g_AF[fa],      scA1 = g_AF[fa + 1],      scA2 = g_AF[fa + 2],      scA3 = g_AF[fa + 3];
    float shA0 = g_AF[HF + fa], shA1 = g_AF[HF + fa + 1], shA2 = g_AF[HF + fa + 2], shA3 = g_AF[HF + fa + 3];
    float scB0 = g_AF[fb],      scB1 = g_AF[fb + 1],      scB2 = g_AF[fb + 2],      scB3 = g_AF[fb + 3];
    float shB0 = g_AF[HF + fb], shB1 = g_AF[HF + fb + 1], shB2 = g_AF[HF + fb + 2], shB3 = g_AF[HF + fb + 3];

    int cur = sI1[eg * 8];
    float m0 = 0.f, m1 = 0.f, m2 = 0.f, m3 = 0.f;
    #pragma unroll
    for (int j = 0; j < 8; j++) {
        int node = sI1[eg * 8 + j];
        if (node != cur) {
            float* d = g_ACC + (size_t)cur * NF + fa;
            atomicAdd(d, m0); atomicAdd(d + 1, m1); atomicAdd(d + 2, m2); atomicAdd(d + 3, m3);
            m0 = m1 = m2 = m3 = 0.f;
            cur = node;
        }
        float2 v0 = unpk(acc[j][0]), v1 = unpk(acc[j][1]);
        float2 v2 = unpk(acc[j][2]), v3 = unpk(acc[j][3]);
        m0 += sig_f(v0.x * scA0 + shA0) * sp_f(v2.x * scB0 + shB0);
        m1 += sig_f(v0.y * scA1 + shA1) * sp_f(v2.y * scB1 + shB1);
        m2 += sig_f(v1.x * scA2 + shA2) * sp_f(v3.x * scB2 + shB2);
        m3 += sig_f(v1.y * scA3 + shA3) * sp_f(v3.y * scB3 + shB3);
    }
    {
        float* d = g_ACC + (size_t)cur * NF + fa;
        atomicAdd(d, m0); atomicAdd(d + 1, m1); atomicAdd(d + 2, m2); atomicAdd(d + 3, m3);
    }
}

// ---------------- node BN stats + apply ----------------
__global__ void k_nstats() {
    __shared__ float s1[NF], s2[NF];
    int tid = threadIdx.x;
    if (tid < NF) { s1[tid] = 0.f; s2[tid] = 0.f; }
    __syncthreads();
    float a1 = 0.f, a2 = 0.f;
    int f = tid & 63;
    for (int i = blockIdx.x * 256 + tid; i < NN * NF; i += gridDim.x * 256) {
        float nm = g_ACC[i] * g_DIf[i >> 6];
        a1 += nm; a2 += nm * nm;
    }
    atomicAdd(&s1[f], a1); atomicAdd(&s2[f], a2);
    __syncthreads();
    if (tid < NF) {
        atomicAdd(&g_NS[tid], (double)s1[tid]);
        atomicAdd(&g_NS[NF + tid], (double)s2[tid]);
    }
}

__global__ void k_nfin(const float* __restrict__ g2, const float* __restrict__ be2, int layer) {
    int f = threadIdx.x;  // 64
    double mean = g_NS[f] / (double)NN;
    double var  = g_NS[NF + f] / (double)NN - mean * mean;
    float istd = (float)rsqrt(var + 1e-5);
    float sc = g2[layer * NF + f] * istd;
    g_NAF[f] = sc;
    g_NAF[NF + f] = be2[layer * NF + f] - (float)mean * sc;
}

__global__ void k_napply() {
    for (int i = blockIdx.x * 256 + threadIdx.x; i < NN * NF; i += gridDim.x * 256) {
        int f = i & 63;
        float nm = g_ACC[i] * g_DIf[i >> 6];
        float v = g_X[i] + nm * g_NAF[f] + g_NAF[NF + f];
        g_X[i] = sp_f(v);
    }
}

// ---------------- readout ----------------
__global__ void k_cryacc(const int* __restrict__ idx3) {
    int i = blockIdx.x * 256 + threadIdx.x;   // NN*NF
    int n = i >> 6, f = i & 63;
    atomicAdd(&g_CRY[idx3[n] * NF + f], g_X[i]);
}

__global__ void k_head(const float* __restrict__ Wc, const float* __restrict__ bc,
                       const float* __restrict__ Wo, const float* __restrict__ bo,
                       float* __restrict__ out) {
    __shared__ float c[NF];
    __shared__ float r0s[4], r1s[4];
    int cid = blockIdx.x, tid = threadIdx.x;   // 128 threads
    if (tid < NF) {
        int cnt = g_CNT[cid];
        c[tid] = g_CRY[cid * NF + tid] / (float)max(cnt, 1);
    }
    __syncthreads();
    float acc = bc[tid];
    #pragma unroll
    for (int k = 0; k < NF; k++) acc += c[k] * Wc[k * HF + tid];
    float h = sp_f(acc);
    float o0 = h * Wo[tid * 2], o1 = h * Wo[tid * 2 + 1];
    #pragma unroll
    for (int s = 16; s; s >>= 1) {
        o0 += __shfl_down_sync(0xffffffffu, o0, s);
        o1 += __shfl_down_sync(0xffffffffu, o1, s);
    }
    if ((tid & 31) == 0) { r0s[tid >> 5] = o0; r1s[tid >> 5] = o1; }
    __syncthreads();
    if (tid == 0) {
        out[cid * 2]     = r0s[0] + r0s[1] + r0s[2] + r0s[3] + bo[0];
        out[cid * 2 + 1] = r1s[0] + r1s[1] + r1s[2] + r1s[3] + bo[1];
    }
}

// ---------------- launch ----------------
extern "C" void kernel_launch(void* const* d_in, const int* in_sizes, int n_in,
                              void* d_out, int out_size) {
    const int*   node_fea = (const int*)  d_in[0];
    const float* edge_fea = (const float*)d_in[1];
    const int*   idx1     = (const int*)  d_in[2];
    const int*   idx2     = (const int*)  d_in[3];
    const int*   idx3     = (const int*)  d_in[4];
    const float* emb      = (const float*)d_in[5];
    const float* Wf       = (const float*)d_in[6];
    const float* bf       = (const float*)d_in[7];
    const float* g1       = (const float*)d_in[8];
    const float* be1      = (const float*)d_in[9];
    const float* g2       = (const float*)d_in[10];
    const float* be2      = (const float*)d_in[11];
    const float* Wc       = (const float*)d_in[12];
    const float* bc       = (const float*)d_in[13];
    const float* Wo       = (const float*)d_in[14];
    const float* bo       = (const float*)d_in[15];
    float* out = (float*)d_out;

    int *dDEG, *dDEG2, *dSTART, *dCUR, *dSTART2, *dCUR2, *dESRC, *dESRC2;
    float *dD1f, *dD2f, *dDIf, *dSCR;
    cudaGetSymbolAddress((void**)&dDEG, g_DEG);
    cudaGetSymbolAddress((void**)&dDEG2, g_DEG2);
    cudaGetSymbolAddress((void**)&dSTART, g_START);
    cudaGetSymbolAddress((void**)&dCUR, g_CUR);
    cudaGetSymbolAddress((void**)&dSTART2, g_START2);
    cudaGetSymbolAddress((void**)&dCUR2, g_CUR2);
    cudaGetSymbolAddress((void**)&dESRC, g_ESRC);
    cudaGetSymbolAddress((void**)&dESRC2, g_ESRC2);
    cudaGetSymbolAddress((void**)&dD1f, g_D1f);
    cudaGetSymbolAddress((void**)&dD2f, g_D2f);
    cudaGetSymbolAddress((void**)&dDIf, g_DIf);
    cudaGetSymbolAddress((void**)&dSCR, g_SCR);

    k_pre<<<500, 256>>>();
    k_embed<<<6250, 256>>>(node_fea, emb);
    k_deg<<<6250, 256>>>(idx1, dDEG);
    k_deg<<<6250, 256>>>(idx2, dDEG2);
    k_cnt3<<<391, 256>>>(idx3);
    // sort by idx1
    k_scan1<<<391, 256>>>(dDEG);
    k_scan2<<<1, 512>>>();
    k_scan3<<<391, 256>>>(dDEG, dSTART, dCUR, dD1f, dDIf);
    k_perm<<<6250, 256>>>(idx1, dCUR, dESRC);
    // sort by idx2
    k_scan1<<<391, 256>>>(dDEG2);
    k_scan2<<<1, 512>>>();
    k_scan3<<<391, 256>>>(dDEG2, dSTART2, dCUR2, dD2f, dSCR);
    k_perm<<<6250, 256>>>(idx2, dCUR2, dESRC2);
    k_permidx<<<6250, 256>>>(idx1, idx2);
    {
        size_t tot = (size_t)NE * EFD;
        int blocks = (int)((tot + 255) / 256);
        k_permef<<<blocks, 256>>>(edge_fea);
    }
    k_S1<<<25000, 256>>>();
    k_S2<<<25000, 256>>>(edge_fea);
    k_G33<<<512, 256>>>();

    for (int l = 0; l < 3; l++) {
        k_zlayer<<<2048, 256>>>();
        dim3 gg(1563, 2);
        k_nodegemm<<<gg, 256>>>(Wf, l);
        k_T<<<25000, 256>>>();
        k_gram<<<128, 256>>>();
        k_statfin<<<128, 256>>>(Wf, bf, g1, be1, l);
        k_edgeF<<<12500, 256>>>(Wf, bf, l);
        k_nstats<<<1024, 256>>>();
        k_nfin<<<1, 64>>>(g2, be2, l);
        k_napply<<<2048, 256>>>();
    }
    k_cryacc<<<25000, 256>>>(idx3);
    k_head<<<2000, 128>>>(Wc, bc, Wo, bo, out);
}

// round 7
// speedup vs baseline: 1.1653x; 1.1653x over previous
#include <cuda_runtime.h>
#include <cuda_fp16.h>
#include <math.h>

#define NN 100000
#define NE 1600000
#define NC 2000
#define NF 64
#define EFD 41
#define HF 128
#define DIN 169

typedef unsigned long long ull;
typedef unsigned int uint;

// ---------------- scratch (static __device__, no allocations) ----------------
__device__ float   g_X[NN * NF];           // node features
__device__ __half  g_P1h[NN * HF];         // X @ Wf[0:64]   (fp16)  25.6MB
__device__ __half  g_P2h[NN * HF];         // X @ Wf[64:128] (fp16)  25.6MB
__device__ __half2 g_Zh[(size_t)NE * 64];  // z pre-BN packed (gate,conv) 409.6MB
__device__ float   g_EFS[(size_t)NE * EFD];// edge features in sorted order 262.4MB
__device__ int     g_I1S[NE], g_I2S[NE];   // endpoints in sorted order
__device__ float   g_ACC[NN * NF];         // per-node msg means
__device__ int     g_DEG[NN];
__device__ int     g_CNT[NC];
__device__ float   g_CRY[NC * NF];
__device__ double  g_S[2 * HF];            // edge BN sum / sumsq
__device__ double  g_NS[2 * NF];           // node BN sum / sumsq
__device__ float   g_AF[2 * HF];           // edge BN scale/shift
__device__ float   g_NAF[2 * NF];          // node BN scale/shift
// counting-sort infra
__device__ int g_TMP[NN];
__device__ int g_BS[512];
__device__ int g_BSX[512];
__device__ int g_START[NN];
__device__ int g_CUR[NN];
__device__ int g_ESRC[NE];

// dynamic smem layout for k_edge1 (uint words):
//   sE  [0, 128*52)            edge features tf32, stride 52 (conflict-free A loads)
//   sW  [6656, 6656+48*136)    W tf32, stride 136 (conflict-free B loads)
//   sI1 [13184,13312) sI2 [13312,13440)
//   sS1 [13440,13568) sS2 [13568,13696)  (float)
#define SE_OFF   0
#define SE_STR   52
#define SW_OFF   6656
#define SW_STR   136
#define SI1_OFF  13184
#define SI2_OFF  13312
#define SS1_OFF  13440
#define SS2_OFF  13568
#define SMEM_WORDS 13696
#define SMEM_BYTES (SMEM_WORDS * 4)

// ---------------- helpers ----------------
__device__ __forceinline__ ull pack2(float x) {
    ull r; asm("mov.b64 %0, {%1, %1};" : "=l"(r) : "f"(x)); return r;
}
__device__ __forceinline__ void ffma2(ull& d, ull a, ull b) {
    asm("fma.rn.f32x2 %0, %1, %2, %0;" : "+l"(d) : "l"(a), "l"(b));
}
__device__ __forceinline__ float2 unpk(ull v) {
    float2 r; asm("mov.b64 {%0, %1}, %2;" : "=f"(r.x), "=f"(r.y) : "l"(v)); return r;
}
__device__ __forceinline__ float sp_f(float x) {
    return fmaxf(x, 0.f) + __logf(1.f + __expf(-fabsf(x)));
}
__device__ __forceinline__ float sig_f(float x) {
    return __fdividef(1.f, 1.f + __expf(-x));
}
__device__ __forceinline__ float2 h2f(uint u) {
    __half2 h = *(__half2*)&u; return __half22float2(h);
}
__device__ __forceinline__ uint f2tf(float v) {
    uint r; asm("cvt.rna.tf32.f32 %0, %1;" : "=r"(r) : "f"(v)); return r;
}
__device__ __forceinline__ void mma_tf32(float* d, const uint* a, const uint* b) {
    asm volatile("mma.sync.aligned.m16n8k8.row.col.f32.tf32.tf32.f32 "
        "{%0,%1,%2,%3}, {%4,%5,%6,%7}, {%8,%9}, {%0,%1,%2,%3};"
        : "+f"(d[0]), "+f"(d[1]), "+f"(d[2]), "+f"(d[3])
        : "r"(a[0]), "r"(a[1]), "r"(a[2]), "r"(a[3]), "r"(b[0]), "r"(b[1]));
}

// ---------------- setup kernels ----------------
__global__ void k_pre() {
    int i = blockIdx.x * 256 + threadIdx.x;
    if (i < NN) g_DEG[i] = 0;
    if (i < NC) g_CNT[i] = 0;
    if (i < NC * NF) g_CRY[i] = 0.f;
}

__global__ void k_embed(const int* __restrict__ nf, const float* __restrict__ emb) {
    int i = blockIdx.x * 256 + threadIdx.x;       // NN*16
    if (i >= NN * 16) return;
    int n = i >> 4, c = i & 15;
    int v = nf[n];
    float4 val = ((const float4*)(emb + (size_t)v * NF))[c];
    ((float4*)(g_X + (size_t)n * NF))[c] = val;
}

__global__ void k_deg(const int* __restrict__ idx1) {
    int e = blockIdx.x * 256 + threadIdx.x;
    if (e < NE) atomicAdd(&g_DEG[idx1[e]], 1);
}

__global__ void k_cnt3(const int* __restrict__ idx3) {
    int n = blockIdx.x * 256 + threadIdx.x;
    if (n < NN) atomicAdd(&g_CNT[idx3[n]], 1);
}

// ---------------- counting sort ----------------
__global__ void k_scan1() {
    __shared__ int s[256];
    int tid = threadIdx.x;
    int n = blockIdx.x * 256 + tid;
    int d = (n < NN) ? g_DEG[n] : 0;
    s[tid] = d;
    __syncthreads();
    for (int off = 1; off < 256; off <<= 1) {
        int v = (tid >= off) ? s[tid - off] : 0;
        __syncthreads();
        s[tid] += v;
        __syncthreads();
    }
    if (n < NN) g_TMP[n] = s[tid] - d;
    if (tid == 255) g_BS[blockIdx.x] = s[255];
}

__global__ void k_scan2() {
    __shared__ int s[512];
    int tid = threadIdx.x;
    int d = (tid < 391) ? g_BS[tid] : 0;
    s[tid] = d;
    __syncthreads();
    for (int off = 1; off < 512; off <<= 1) {
        int v = (tid >= off) ? s[tid - off] : 0;
        __syncthreads();
        s[tid] += v;
        __syncthreads();
    }
    if (tid < 391) g_BSX[tid] = s[tid] - d;
}

__global__ void k_scan3() {
    int n = blockIdx.x * 256 + threadIdx.x;
    if (n < NN) {
        int st = g_TMP[n] + g_BSX[blockIdx.x];
        g_START[n] = st;
        g_CUR[n] = st;
    }
}

__global__ void k_perm(const int* __restrict__ idx1) {
    int e = blockIdx.x * 256 + threadIdx.x;
    if (e < NE) {
        int pos = atomicAdd(&g_CUR[idx1[e]], 1);
        g_ESRC[pos] = e;
    }
}

__global__ void k_permidx(const int* __restrict__ idx1, const int* __restrict__ idx2) {
    int p = blockIdx.x * 256 + threadIdx.x;
    if (p < NE) {
        int e = g_ESRC[p];
        g_I1S[p] = idx1[e];
        g_I2S[p] = idx2[e];
    }
}

__global__ void k_permef(const float* __restrict__ ef) {
    size_t i = (size_t)blockIdx.x * 256 + threadIdx.x;   // NE*EFD total
    if (i >= (size_t)NE * EFD) return;
    int p = (int)(i / EFD), c = (int)(i - (size_t)p * EFD);
    g_EFS[i] = __ldg(ef + (size_t)g_ESRC[p] * EFD + c);
}

__global__ void k_zstat() {
    int tid = threadIdx.x;  // 256
    g_S[tid] = 0.0;
    if (tid < 2 * NF) g_NS[tid] = 0.0;
}

// ---------------- node GEMM: P1/P2(half) = X @ Wf[l][half*64 : +64] --------
__global__ __launch_bounds__(256) void k_nodegemm(const float* __restrict__ Wf, int layer) {
    __shared__ float sW[64 * HF];   // 32 KB
    __shared__ float sX[64 * NF];   // 16 KB
    const float* Wb = Wf + ((size_t)layer * DIN + blockIdx.y * 64) * HF;
    int tid = threadIdx.x;
    #pragma unroll 4
    for (int i = tid; i < 64 * HF; i += 256) sW[i] = Wb[i];
    int n0 = blockIdx.x * 64;
    for (int i = tid; i < 64 * NF; i += 256) {
        int r = i >> 6, c = i & 63, n = n0 + r;
        sX[i] = (n < NN) ? g_X[(size_t)n * NF + c] : 0.f;
    }
    __syncthreads();
    int fg = tid & 15, eg = tid >> 4;
    int fa = fg * 4, fb = 64 + fg * 4;
    ull acc[4][4];
    #pragma unroll
    for (int j = 0; j < 4; j++)
        #pragma unroll
        for (int q = 0; q < 4; q++) acc[j][q] = 0ULL;
    #pragma unroll 1
    for (int k = 0; k < 64; k++) {
        ulonglong2 wa = *(const ulonglong2*)(sW + k * HF + fa);
        ulonglong2 wb = *(const ulonglong2*)(sW + k * HF + fb);
        #pragma unroll
        for (int j = 0; j < 4; j++) {
            ull a = pack2(sX[(eg * 4 + j) * NF + k]);
            ffma2(acc[j][0], a, wa.x); ffma2(acc[j][1], a, wa.y);
            ffma2(acc[j][2], a, wb.x); ffma2(acc[j][3], a, wb.y);
        }
    }
    __half* out = blockIdx.y ? g_P2h : g_P1h;
    #pragma unroll
    for (int j = 0; j < 4; j++) {
        int n = n0 + eg * 4 + j;
        if (n < NN) {
            float2 v0 = unpk(acc[j][0]), v1 = unpk(acc[j][1]);
            float2 v2 = unpk(acc[j][2]), v3 = unpk(acc[j][3]);
            __half2 ha[2], hb[2];
            ha[0] = __floats2half2_rn(v0.x, v0.y);
            ha[1] = __floats2half2_rn(v1.x, v1.y);
            hb[0] = __floats2half2_rn(v2.x, v2.y);
            hb[1] = __floats2half2_rn(v3.x, v3.y);
            *(uint2*)(out + (size_t)n * HF + fa) = *(uint2*)ha;
            *(uint2*)(out + (size_t)n * HF + fb) = *(uint2*)hb;
        }
    }
}

// ---------------- edge pass 1 (tf32 tensor cores): z -> Zh (fp16) + BN stats
// 128 edges x 128 outputs per block, K padded 41->48. 8 warps:
//   warp w: rows m_base=(w&3)*32, cols c0=(w>>2)*32 (gate) and c0+64 (conv).
//   n-tiles: nt 0..3 gate at c0+8nt, nt 4..7 conv at c0+64+8(nt-4).
__global__ __launch_bounds__(256) void k_edge1(
    const float* __restrict__ Wf, const float* __restrict__ bfp, int layer)
{
    extern __shared__ uint smx[];
    float* sS1f = (float*)(smx + SS1_OFF);
    float* sS2f = (float*)(smx + SS2_OFF);
    int*   sI1  = (int*)(smx + SI1_OFF);
    int*   sI2  = (int*)(smx + SI2_OFF);
    const float* Wb = Wf + ((size_t)layer * DIN + 128) * HF;
    int tid = threadIdx.x;
    size_t p0 = (size_t)blockIdx.x * 128;

    // load W (tf32 bits), rows 41..47 zero
    for (int i = tid; i < 48 * 128; i += 256) {
        int k = i >> 7, n = i & 127;
        smx[SW_OFF + k * SW_STR + n] = (k < EFD) ? f2tf(Wb[k * HF + n]) : 0u;
    }
    // load edge features (tf32 bits), cols 41..47 zero
    {
        const float* efb = g_EFS + p0 * EFD;
        for (int i = tid; i < 128 * 48; i += 256) {
            int r = i / 48, c = i - r * 48;
            smx[SE_OFF + r * SE_STR + c] = (c < EFD) ? f2tf(__ldcs(efb + r * EFD + c)) : 0u;
        }
    }
    if (tid < 128) {
        sI1[tid] = g_I1S[p0 + tid];
        sI2[tid] = g_I2S[p0 + tid];
        sS1f[tid] = 0.f; sS2f[tid] = 0.f;
    }
    __syncthreads();

    int w = tid >> 5;
    int lane = tid & 31;
    int gid = lane >> 2, tig = lane & 3;
    int m_base = (w & 3) * 32;
    int c0 = (w >> 2) * 32;

    float acc[2][8][4];
    #pragma unroll
    for (int mt = 0; mt < 2; mt++)
        #pragma unroll
        for (int nt = 0; nt < 8; nt++)
            #pragma unroll
            for (int q = 0; q < 4; q++) acc[mt][nt][q] = 0.f;

    #pragma unroll 1
    for (int ks = 0; ks < 6; ks++) {
        int k0 = ks * 8;
        uint b[8][2];
        #pragma unroll
        for (int nt = 0; nt < 8; nt++) {
            int col = (nt < 4 ? c0 + 8 * nt : c0 + 64 + 8 * (nt - 4)) + gid;
            b[nt][0] = smx[SW_OFF + (k0 + tig) * SW_STR + col];
            b[nt][1] = smx[SW_OFF + (k0 + tig + 4) * SW_STR + col];
        }
        uint a[2][4];
        #pragma unroll
        for (int mt = 0; mt < 2; mt++) {
            int row = m_base + 16 * mt + gid;
            a[mt][0] = smx[SE_OFF + row * SE_STR + k0 + tig];
            a[mt][1] = smx[SE_OFF + (row + 8) * SE_STR + k0 + tig];
            a[mt][2] = smx[SE_OFF + row * SE_STR + k0 + tig + 4];
            a[mt][3] = smx[SE_OFF + (row + 8) * SE_STR + k0 + tig + 4];
        }
        #pragma unroll
        for (int mt = 0; mt < 2; mt++)
            #pragma unroll
            for (int nt = 0; nt < 8; nt++)
                mma_tf32(acc[mt][nt], a[mt], b[nt]);
    }

    // epilogue: add P1[i1]+P2[i2]+bias, BN stats, Zh fp16 store
    const float* bfl = bfp + layer * HF;
    float st1[16], st2[16];
    #pragma unroll
    for (int q = 0; q < 16; q++) { st1[q] = 0.f; st2[q] = 0.f; }

    #pragma unroll
    for (int mt = 0; mt < 2; mt++) {
        #pragma unroll
        for (int r2 = 0; r2 < 2; r2++) {
            int r = m_base + 16 * mt + gid + 8 * r2;
            int i1 = sI1[r], i2 = sI2[r];
            const __half* p1 = g_P1h + (size_t)i1 * HF;
            const __half* p2 = g_P2h + (size_t)i2 * HF;
            int ai = r2 * 2;
            #pragma unroll
            for (int nt = 0; nt < 4; nt++) {
                int cg = c0 + 8 * nt + 2 * tig;
                float2 a1g = h2f(*(const uint*)(p1 + cg));
                float2 a2g = h2f(*(const uint*)(p2 + cg));
                float2 a1c = h2f(*(const uint*)(p1 + cg + 64));
                float2 a2c = h2f(*(const uint*)(p2 + cg + 64));
                float2 bg = *(const float2*)(bfl + cg);
                float2 bc2 = *(const float2*)(bfl + cg + 64);
                float g0 = acc[mt][nt][ai]     + a1g.x + a2g.x + bg.x;
                float g1v = acc[mt][nt][ai + 1] + a1g.y + a2g.y + bg.y;
                float v0 = acc[mt][nt + 4][ai]     + a1c.x + a2c.x + bc2.x;
                float v1 = acc[mt][nt + 4][ai + 1] + a1c.y + a2c.y + bc2.y;
                int q = nt * 2;
                st1[q] += g0;      st2[q] += g0 * g0;
                st1[q + 1] += g1v; st2[q + 1] += g1v * g1v;
                st1[8 + q] += v0;      st2[8 + q] += v0 * v0;
                st1[8 + q + 1] += v1;  st2[8 + q + 1] += v1 * v1;
                __half2 hz0 = __floats2half2_rn(g0, v0);
                __half2 hz1 = __floats2half2_rn(g1v, v1);
                uint uz0 = *(uint*)&hz0, uz1 = *(uint*)&hz1;
                ull zz = (ull)uz0 | ((ull)uz1 << 32);
                __stcs((ull*)(g_Zh + (p0 + r) * 64 + cg), zz);
            }
        }
    }
    // stats: smem atomic per owned column
    #pragma unroll
    for (int q = 0; q < 8; q++) {
        int col = c0 + 8 * (q >> 1) + 2 * tig + (q & 1);
        atomicAdd(&sS1f[col], st1[q]);
        atomicAdd(&sS2f[col], st2[q]);
        atomicAdd(&sS1f[col + 64], st1[8 + q]);
        atomicAdd(&sS2f[col + 64], st2[8 + q]);
    }
    __syncthreads();
    if (tid < HF) {
        atomicAdd(&g_S[tid], (double)sS1f[tid]);
        atomicAdd(&g_S[HF + tid], (double)sS2f[tid]);
    }
}

__global__ void k_efin(const float* __restrict__ g1, const float* __restrict__ be1, int layer) {
    int f = threadIdx.x;  // 128
    double mean = g_S[f] / (double)NE;
    double var  = g_S[HF + f] / (double)NE - mean * mean;
    float istd = (float)rsqrt(var + 1e-5);
    float sc = g1[layer * HF + f] * istd;
    g_AF[f] = sc;
    g_AF[HF + f] = be1[layer * HF + f] - (float)mean * sc;
}

// ---------------- edge pass 2: segment reduction (no atomics) ---------------
__global__ __launch_bounds__(256) void k_edge2() {
    int t = threadIdx.x;
    int n = blockIdx.x * 4 + (t >> 6);
    int f = t & 63;
    if (n >= NN) return;
    float sc_a = g_AF[f],      sh_a = g_AF[HF + f];
    float sc_b = g_AF[64 + f], sh_b = g_AF[HF + 64 + f];
    int st = g_START[n], dg = g_DEG[n];
    float sum = 0.f;
    const uint* zp = (const uint*)(g_Zh + (size_t)st * 64 + f);
    #pragma unroll 4
    for (int q = 0; q < dg; q++) {
        uint u = __ldcs(zp + (size_t)q * 64);
        float2 v = h2f(u);
        float a = v.x * sc_a + sh_a;
        float b = v.y * sc_b + sh_b;
        sum += sig_f(a) * sp_f(b);
    }
    g_ACC[(size_t)n * NF + f] = sum / (float)max(dg, 1);
}

// ---------------- node BN stats + apply ----------------
__global__ void k_nstats() {
    __shared__ float s1[NF], s2[NF];
    int tid = threadIdx.x;
    if (tid < NF) { s1[tid] = 0.f; s2[tid] = 0.f; }
    __syncthreads();
    float a1 = 0.f, a2 = 0.f;
    int f = tid & 63;
    for (int i = blockIdx.x * 256 + tid; i < NN * NF; i += gridDim.x * 256) {
        float nm = g_ACC[i];
        a1 += nm; a2 += nm * nm;
    }
    atomicAdd(&s1[f], a1); atomicAdd(&s2[f], a2);
    __syncthreads();
    if (tid < NF) {
        atomicAdd(&g_NS[tid], (double)s1[tid]);
        atomicAdd(&g_NS[NF + tid], (double)s2[tid]);
    }
}

__global__ void k_nfin(const float* __restrict__ g2, const float* __restrict__ be2, int layer) {
    int f = threadIdx.x;  // 64
    double mean = g_NS[f] / (double)NN;
    double var  = g_NS[NF + f] / (double)NN - mean * mean;
    float istd = (float)rsqrt(var + 1e-5);
    float sc = g2[layer * NF + f] * istd;
    g_NAF[f] = sc;
    g_NAF[NF + f] = be2[layer * NF + f] - (float)mean * sc;
}

__global__ void k_napply() {
    for (int i = blockIdx.x * 256 + threadIdx.x; i < NN * NF; i += gridDim.x * 256) {
        int f = i & 63;
        float v = g_X[i] + g_ACC[i] * g_NAF[f] + g_NAF[NF + f];
        g_X[i] = sp_f(v);
    }
}

// ---------------- readout ----------------
__global__ void k_cryacc(const int* __restrict__ idx3) {
    int i = blockIdx.x * 256 + threadIdx.x;   // NN*NF
    int n = i >> 6, f = i & 63;
    atomicAdd(&g_CRY[idx3[n] * NF + f], g_X[i]);
}

__global__ void k_head(const float* __restrict__ Wc, const float* __restrict__ bc,
                       const float* __restrict__ Wo, const float* __restrict__ bo,
                       float* __restrict__ out) {
    __shared__ float c[NF];
    __shared__ float r0s[4], r1s[4];
    int cid = blockIdx.x, tid = threadIdx.x;   // 128 threads
    if (tid < NF) {
        int cnt = g_CNT[cid];
        c[tid] = g_CRY[cid * NF + tid] / (float)max(cnt, 1);
    }
    __syncthreads();
    float acc = bc[tid];
    #pragma unroll
    for (int k = 0; k < NF; k++) acc += c[k] * Wc[k * HF + tid];
    float h = sp_f(acc);
    float o0 = h * Wo[tid * 2], o1 = h * Wo[tid * 2 + 1];
    #pragma unroll
    for (int s = 16; s; s >>= 1) {
        o0 += __shfl_down_sync(0xffffffffu, o0, s);
        o1 += __shfl_down_sync(0xffffffffu, o1, s);
    }
    if ((tid & 31) == 0) { r0s[tid >> 5] = o0; r1s[tid >> 5] = o1; }
    __syncthreads();
    if (tid == 0) {
        out[cid * 2]     = r0s[0] + r0s[1] + r0s[2] + r0s[3] + bo[0];
        out[cid * 2 + 1] = r1s[0] + r1s[1] + r1s[2] + r1s[3] + bo[1];
    }
}

// ---------------- launch ----------------
extern "C" void kernel_launch(void* const* d_in, const int* in_sizes, int n_in,
                              void* d_out, int out_size) {
    const int*   node_fea = (const int*)  d_in[0];
    const float* edge_fea = (const float*)d_in[1];
    const int*   idx1     = (const int*)  d_in[2];
    const int*   idx2     = (const int*)  d_in[3];
    const int*   idx3     = (const int*)  d_in[4];
    const float* emb      = (const float*)d_in[5];
    const float* Wf       = (const float*)d_in[6];
    const float* bf       = (const float*)d_in[7];
    const float* g1       = (const float*)d_in[8];
    const float* be1      = (const float*)d_in[9];
    const float* g2       = (const float*)d_in[10];
    const float* be2      = (const float*)d_in[11];
    const float* Wc       = (const float*)d_in[12];
    const float* bc       = (const float*)d_in[13];
    const float* Wo       = (const float*)d_in[14];
    const float* bo       = (const float*)d_in[15];
    float* out = (float*)d_out;

    cudaFuncSetAttribute(k_edge1, cudaFuncAttributeMaxDynamicSharedMemorySize, SMEM_BYTES);

    k_pre<<<500, 256>>>();
    k_embed<<<6250, 256>>>(node_fea, emb);
    k_deg<<<6250, 256>>>(idx1);
    k_cnt3<<<391, 256>>>(idx3);
    k_scan1<<<391, 256>>>();
    k_scan2<<<1, 512>>>();
    k_scan3<<<391, 256>>>();
    k_perm<<<6250, 256>>>(idx1);
    k_permidx<<<6250, 256>>>(idx1, idx2);
    {
        size_t tot = (size_t)NE * EFD;
        int blocks = (int)((tot + 255) / 256);
        k_permef<<<blocks, 256>>>(edge_fea);
    }
    for (int l = 0; l < 3; l++) {
        k_zstat<<<1, 256>>>();
        dim3 gg(1563, 2);
        k_nodegemm<<<gg, 256>>>(Wf, l);
        k_edge1<<<12500, 256, SMEM_BYTES>>>(Wf, bf, l);
        k_efin<<<1, 128>>>(g1, be1, l);
        k_edge2<<<25000, 256>>>();
        k_nstats<<<1024, 256>>>();
        k_nfin<<<1, 64>>>(g2, be2, l);
        k_napply<<<2048, 256>>>();
    }
    k_cryacc<<<25000, 256>>>(idx3);
    k_head<<<2000, 128>>>(Wc, bc, Wo, bo, out);
}